// round 7
// baseline (speedup 1.0000x reference)
#include <cuda_runtime.h>
#include <cuda_fp16.h>
#include <cstdint>

// ---------------------------------------------------------------------------
// GroupAttention (Swin window attention)
// B=32, N=4096 (64x64), C=128, WS=8 -> G=64 windows, S=64 tokens/window
// heads=4, hd=32.
// Round 7: one fused kernel (QKV+attention+proj), 1 window/CTA (2 CTAs/SM),
// ldmatrix fragment loads, fp16 weights pre-converted.
// ---------------------------------------------------------------------------

#define B_    32
#define NTOK  4096
#define C_    128
#define G_    64
#define S_    64
#define NH    4
#define HD    32

__device__ __half g_wq_h[384 * 128];
__device__ __half g_wp_h[128 * 128];

__device__ __forceinline__ int token_index(int g, int s) {
    return ((g >> 3) << 9) + ((s >> 3) << 6) + ((g & 7) << 3) + (s & 7);
}

__device__ __forceinline__ uint32_t h2u(__half2 h) {
    return *(uint32_t*)&h;
}

__device__ __forceinline__ uint32_t smem_u32(const void* p) {
    uint32_t a;
    asm("{ .reg .u64 t; cvta.to.shared.u64 t, %1; cvt.u32.u64 %0, t; }"
        : "=r"(a) : "l"(p));
    return a;
}

__device__ __forceinline__ void mma_f16(float* c, const uint32_t* a,
                                        const uint32_t* b) {
    asm volatile(
        "mma.sync.aligned.m16n8k16.row.col.f32.f16.f16.f32 "
        "{%0,%1,%2,%3}, {%4,%5,%6,%7}, {%8,%9}, {%0,%1,%2,%3};"
        : "+f"(c[0]), "+f"(c[1]), "+f"(c[2]), "+f"(c[3])
        : "r"(a[0]), "r"(a[1]), "r"(a[2]), "r"(a[3]), "r"(b[0]), "r"(b[1]));
}

__device__ __forceinline__ void ldmx4(uint32_t* r, uint32_t addr) {
    asm volatile(
        "ldmatrix.sync.aligned.m8n8.x4.shared.b16 {%0,%1,%2,%3}, [%4];"
        : "=r"(r[0]), "=r"(r[1]), "=r"(r[2]), "=r"(r[3]) : "r"(addr));
}

// smem strides in halfwords (word-stride % 32 == 4 -> ldmatrix conflict-free)
#define LDH 136
#define VLDH 72

// byte offsets; Xs doubles as O after QKV
#define OFF_X  0                        // Xs/Oh [64][136]  : 17408
#define OFF_W  17408                    // Ws   [128][136]  : 34816
#define OFF_Q  52224                    // Qh    [64][136]  : 17408
#define OFF_K  69632                    // Kh    [64][136]  : 17408
#define OFF_V  87040                    // Vt   [128][72]   : 18432
#define SMEM_FUSED 105472               // x2 CTAs = 206 KB / SM

#define SCALE 0.17677669529663687f

// ---------------------------------------------------------------------------
__global__ void __launch_bounds__(256) cvt_weights(const float* __restrict__ wq,
                                                   const float* __restrict__ wp) {
    int idx = blockIdx.x * 256 + threadIdx.x;    // 16384 float4 slots
    if (idx < 12288) {
        float4 v = ((const float4*)wq)[idx];
        __half2* d = (__half2*)g_wq_h + idx * 2;
        d[0] = __floats2half2_rn(v.x, v.y);
        d[1] = __floats2half2_rn(v.z, v.w);
    } else {
        int j = idx - 12288;
        float4 v = ((const float4*)wp)[j];
        __half2* d = (__half2*)g_wp_h + j * 2;
        d[0] = __floats2half2_rn(v.x, v.y);
        d[1] = __floats2half2_rn(v.z, v.w);
    }
}

// ---------------------------------------------------------------------------
// Fused kernel: one block per window, 256 threads (8 warps), 2 CTAs/SM.
// ---------------------------------------------------------------------------
__global__ void __launch_bounds__(256, 2)
fused_all(const float* __restrict__ x, const float* __restrict__ bp,
          float* __restrict__ out) {
    extern __shared__ char sm[];
    __half* Xs = (__half*)(sm + OFF_X);       // X, then O
    __half* Ws = (__half*)(sm + OFF_W);
    __half* Qh = (__half*)(sm + OFF_Q);
    __half* Kh = (__half*)(sm + OFF_K);
    __half* Vt = (__half*)(sm + OFF_V);

    const uint32_t xb = smem_u32(Xs);
    const uint32_t wb = smem_u32(Ws);
    const uint32_t qb = smem_u32(Qh);
    const uint32_t kb = smem_u32(Kh);
    const uint32_t vb = smem_u32(Vt);

    const int tid = threadIdx.x;
    const int wid = tid >> 5, lane = tid & 31;
    const int lr = lane >> 2, lc = lane & 3;
    const int bg = blockIdx.x;
    const int b = bg >> 6, g = bg & 63;

    // per-thread ldmatrix address components
    const int a_row = lane & 15;              // A-frag row-within-16
    const int a_k8  = (lane >> 4) << 3;       // A-frag k-offset (0/8)
    const int b_row = ((lane >> 4) << 3) + (lane & 7);  // B-frag row-within-16
    const int b_k8  = ((lane >> 3) & 1) << 3;           // B-frag k-offset

    // ---- load x window (gathered), fp32 -> fp16 ----
    #pragma unroll
    for (int it = 0; it < 8; it++) {
        int fidx = tid + it * 256;            // 2048 float4s: 64 rows x 32
        int s = fidx >> 5;
        int c4 = fidx & 31;
        int n = token_index(g, s);
        float4 v = *(const float4*)(x + ((size_t)b * NTOK + n) * C_ + c4 * 4);
        __half2* dst = (__half2*)(Xs + s * LDH + c4 * 4);
        dst[0] = __floats2half2_rn(v.x, v.y);
        dst[1] = __floats2half2_rn(v.z, v.w);
    }

    // ---- QKV GEMM: M=64 x N=128 per chunk; warp tile 16x64 ----
    const int m0 = (wid & 3) * 16;
    const int n0 = (wid >> 2) * 64;

    const uint32_t xfrag = xb + (((m0 + a_row) * LDH) + a_k8) * 2;

    #pragma unroll
    for (int ch = 0; ch < 3; ch++) {
        __syncthreads();                      // Ws free; Xs ready (ch 0)
        #pragma unroll
        for (int it = 0; it < 8; it++) {
            int fidx = tid + it * 256;        // 2048 uint4s: 128 rows x 16
            int r = fidx >> 4;
            int q = fidx & 15;
            uint4 v = *(const uint4*)(g_wq_h + (size_t)(ch * 128 + r) * C_ + q * 8);
            *(uint4*)(Ws + r * LDH + q * 8) = v;
        }
        __syncthreads();

        float c[8][4];
        #pragma unroll
        for (int nj = 0; nj < 8; nj++)
            #pragma unroll
            for (int q = 0; q < 4; q++) c[nj][q] = 0.f;

        #pragma unroll
        for (int kt = 0; kt < 8; kt++) {
            uint32_t a[4];
            ldmx4(a, xfrag + kt * 32);
            #pragma unroll
            for (int np = 0; np < 4; np++) {
                uint32_t bb[4];
                uint32_t baddr = wb +
                    (((n0 + np * 16 + b_row) * LDH) + kt * 16 + b_k8) * 2;
                ldmx4(bb, baddr);
                mma_f16(c[np * 2], a, bb);
                mma_f16(c[np * 2 + 1], a, bb + 2);
            }
        }

        // epilogue: ch0 -> Qh, ch1 -> Kh, ch2 -> Vt (transposed)
        if (ch < 2) {
            __half* Th = (ch == 0) ? Qh : Kh;
            #pragma unroll
            for (int nj = 0; nj < 8; nj++) {
                int col = n0 + nj * 8 + 2 * lc;
                *(__half2*)(Th + (m0 + lr) * LDH + col) =
                    __floats2half2_rn(c[nj][0], c[nj][1]);
                *(__half2*)(Th + (m0 + lr + 8) * LDH + col) =
                    __floats2half2_rn(c[nj][2], c[nj][3]);
            }
        } else {
            #pragma unroll
            for (int nj = 0; nj < 8; nj++) {
                int d = n0 + nj * 8 + 2 * lc;
                int s0 = m0 + lr;
                Vt[d * VLDH + s0]           = __float2half_rn(c[nj][0]);
                Vt[(d + 1) * VLDH + s0]     = __float2half_rn(c[nj][1]);
                Vt[d * VLDH + s0 + 8]       = __float2half_rn(c[nj][2]);
                Vt[(d + 1) * VLDH + s0 + 8] = __float2half_rn(c[nj][3]);
            }
        }
    }
    __syncthreads();   // Q/K/Vt complete; Xs & Ws reusable

    // ---- preload Wp into Ws (overlaps attention math) ----
    #pragma unroll
    for (int it = 0; it < 8; it++) {
        int fidx = tid + it * 256;
        int r = fidx >> 4;
        int q = fidx & 15;
        uint4 v = *(const uint4*)(g_wp_h + (size_t)r * C_ + q * 8);
        *(uint4*)(Ws + r * LDH + q * 8) = v;
    }

    // ---- attention: warp = (head, row-half). 8 warps = 4*2 ----
    const int head = wid >> 1;
    const int hh = head * 32;          // half-offset of head within row
    const int m0a = (wid & 1) * 32;

    // S = Q K^T
    float sf[2][8][4];
    #pragma unroll
    for (int mi = 0; mi < 2; mi++)
        #pragma unroll
        for (int nj = 0; nj < 8; nj++)
            #pragma unroll
            for (int q = 0; q < 4; q++) sf[mi][nj][q] = 0.f;

    #pragma unroll
    for (int kt = 0; kt < 2; kt++) {
        uint32_t a[2][4];
        #pragma unroll
        for (int mi = 0; mi < 2; mi++)
            ldmx4(a[mi], qb + (((m0a + mi * 16 + a_row) * LDH) +
                               hh + kt * 16 + a_k8) * 2);
        #pragma unroll
        for (int np = 0; np < 4; np++) {
            uint32_t bb[4];
            ldmx4(bb, kb + (((np * 16 + b_row) * LDH) + hh + kt * 16 + b_k8) * 2);
            mma_f16(sf[0][np * 2], a[0], bb);
            mma_f16(sf[0][np * 2 + 1], a[0], bb + 2);
            mma_f16(sf[1][np * 2], a[1], bb);
            mma_f16(sf[1][np * 2 + 1], a[1], bb + 2);
        }
    }

    // softmax (rows lr: lo, lr+8: hi within each 16-row group)
    float invlo[2], invhi[2];
    uint32_t ph[2][8][2];
    #pragma unroll
    for (int mi = 0; mi < 2; mi++) {
        float mlo = -1e30f, mhi = -1e30f;
        #pragma unroll
        for (int nj = 0; nj < 8; nj++) {
            mlo = fmaxf(mlo, fmaxf(sf[mi][nj][0], sf[mi][nj][1]));
            mhi = fmaxf(mhi, fmaxf(sf[mi][nj][2], sf[mi][nj][3]));
        }
        mlo = fmaxf(mlo, __shfl_xor_sync(0xffffffffu, mlo, 1));
        mlo = fmaxf(mlo, __shfl_xor_sync(0xffffffffu, mlo, 2));
        mhi = fmaxf(mhi, __shfl_xor_sync(0xffffffffu, mhi, 1));
        mhi = fmaxf(mhi, __shfl_xor_sync(0xffffffffu, mhi, 2));

        float slo = 0.f, shi = 0.f;
        #pragma unroll
        for (int nj = 0; nj < 8; nj++) {
            float e0 = __expf((sf[mi][nj][0] - mlo) * SCALE);
            float e1 = __expf((sf[mi][nj][1] - mlo) * SCALE);
            float e2 = __expf((sf[mi][nj][2] - mhi) * SCALE);
            float e3 = __expf((sf[mi][nj][3] - mhi) * SCALE);
            slo += e0 + e1;
            shi += e2 + e3;
            ph[mi][nj][0] = h2u(__floats2half2_rn(e0, e1));
            ph[mi][nj][1] = h2u(__floats2half2_rn(e2, e3));
        }
        slo += __shfl_xor_sync(0xffffffffu, slo, 1);
        slo += __shfl_xor_sync(0xffffffffu, slo, 2);
        shi += __shfl_xor_sync(0xffffffffu, shi, 1);
        shi += __shfl_xor_sync(0xffffffffu, shi, 2);
        invlo[mi] = 1.f / slo;
        invhi[mi] = 1.f / shi;
    }

    // O = P V (P frags reused directly as A operands)
    float o[2][4][4];
    #pragma unroll
    for (int mi = 0; mi < 2; mi++)
        #pragma unroll
        for (int nj = 0; nj < 4; nj++)
            #pragma unroll
            for (int q = 0; q < 4; q++) o[mi][nj][q] = 0.f;

    #pragma unroll
    for (int kt = 0; kt < 4; kt++) {
        uint32_t a[2][4];
        #pragma unroll
        for (int mi = 0; mi < 2; mi++) {
            a[mi][0] = ph[mi][2 * kt][0];
            a[mi][1] = ph[mi][2 * kt][1];
            a[mi][2] = ph[mi][2 * kt + 1][0];
            a[mi][3] = ph[mi][2 * kt + 1][1];
        }
        #pragma unroll
        for (int np = 0; np < 2; np++) {
            uint32_t bb[4];
            ldmx4(bb, vb + (((hh + np * 16 + b_row) * VLDH) +
                            kt * 16 + b_k8) * 2);
            mma_f16(o[0][np * 2], a[0], bb);
            mma_f16(o[0][np * 2 + 1], a[0], bb + 2);
            mma_f16(o[1][np * 2], a[1], bb);
            mma_f16(o[1][np * 2 + 1], a[1], bb + 2);
        }
    }

    // normalize, store O into Xs buffer
    __half* Oh = Xs;
    #pragma unroll
    for (int mi = 0; mi < 2; mi++) {
        int r = m0a + mi * 16 + lr;
        #pragma unroll
        for (int nj = 0; nj < 4; nj++) {
            int col = hh + nj * 8 + 2 * lc;
            *(__half2*)(Oh + r * LDH + col) =
                __floats2half2_rn(o[mi][nj][0] * invlo[mi],
                                  o[mi][nj][1] * invlo[mi]);
            *(__half2*)(Oh + (r + 8) * LDH + col) =
                __floats2half2_rn(o[mi][nj][2] * invhi[mi],
                                  o[mi][nj][3] * invhi[mi]);
        }
    }
    __syncthreads();   // O complete, Wp loaded

    // ---- proj GEMM: out = O * Wp^T + bias ----
    float c[8][4];
    #pragma unroll
    for (int nj = 0; nj < 8; nj++)
        #pragma unroll
        for (int q = 0; q < 4; q++) c[nj][q] = 0.f;

    #pragma unroll
    for (int kt = 0; kt < 8; kt++) {
        uint32_t a[4];
        ldmx4(a, xfrag + kt * 32);
        #pragma unroll
        for (int np = 0; np < 4; np++) {
            uint32_t bb[4];
            ldmx4(bb, wb + (((n0 + np * 16 + b_row) * LDH) + kt * 16 + b_k8) * 2);
            mma_f16(c[np * 2], a, bb);
            mma_f16(c[np * 2 + 1], a, bb + 2);
        }
    }

    {
        int r = m0 + lr;
        int n0t = token_index(g, r);
        int n1t = token_index(g, r + 8);
        float* r0 = out + ((size_t)b * NTOK + n0t) * C_;
        float* r1 = out + ((size_t)b * NTOK + n1t) * C_;
        #pragma unroll
        for (int nj = 0; nj < 8; nj++) {
            int col = n0 + nj * 8 + 2 * lc;
            float bx = bp[col], by = bp[col + 1];
            *(float2*)(r0 + col) = make_float2(c[nj][0] + bx, c[nj][1] + by);
            *(float2*)(r1 + col) = make_float2(c[nj][2] + bx, c[nj][3] + by);
        }
    }
}

// ---------------------------------------------------------------------------
extern "C" void kernel_launch(void* const* d_in, const int* in_sizes, int n_in,
                              void* d_out, int out_size) {
    (void)in_sizes; (void)n_in; (void)out_size;
    const float* x      = (const float*)d_in[0];
    const float* w_qkv  = (const float*)d_in[1];
    const float* w_proj = (const float*)d_in[2];
    const float* b_proj = (const float*)d_in[3];
    float* out = (float*)d_out;

    cudaFuncSetAttribute(fused_all,
                         cudaFuncAttributeMaxDynamicSharedMemorySize, SMEM_FUSED);

    cvt_weights<<<64, 256>>>(w_qkv, w_proj);
    fused_all<<<B_ * G_, 256, SMEM_FUSED>>>(x, b_proj, out);
}